// round 1
// baseline (speedup 1.0000x reference)
#include <cuda_runtime.h>
#include <math.h>

#define Nn 100000
#define Ee 1600000
#define Hh 64
#define Ll 3
#define Kt 8192
#define CUT 5.0f
#define INVBN 0.9995003747f   // 1/sqrt(1+1e-3)

// ---- scratch (static device arrays: no runtime allocation allowed) ----
__device__ __align__(256) float g_h[Nn * Hh];     // node features, 25.6 MB
__device__ __align__(256) float g_agg[Nn * Hh];   // scatter-add target, 25.6 MB
__device__ float g_table[Ll * Kt];                // fs(d)*cut(d) per layer
__device__ float g_w2s[Ll * Hh];                  // rowsum of fW2
__device__ float g_b2s[Ll];                       // sum of fb2
__device__ float g_mean[Hh];                      // mean accumulator

__device__ __forceinline__ float sp(float x) {    // softplus, stable
    return fmaxf(x, 0.0f) + log1pf(expf(-fabsf(x)));
}

__device__ __forceinline__ void red_add_v4(float4* p, float4 v) {
    asm volatile("red.global.add.v4.f32 [%0], {%1,%2,%3,%4};"
                 :: "l"(p), "f"(v.x), "f"(v.y), "f"(v.z), "f"(v.w) : "memory");
}

// ---- prep: fW2 rowsums, fb2 sums, zero mean accumulator ----
__global__ void prep_kernel(const float* __restrict__ fW2,
                            const float* __restrict__ fb2) {
    int t = threadIdx.x;
    if (t < Ll * Hh) {
        int l = t >> 6, j = t & 63;
        const float* p = fW2 + l * Hh * Hh + j * Hh;
        float s = 0.0f;
        #pragma unroll
        for (int k = 0; k < Hh; k++) s += p[k];
        g_w2s[t] = s;
    }
    if (t < Ll) {
        float s = 0.0f;
        for (int k = 0; k < Hh; k++) s += fb2[t * Hh + k];
        g_b2s[t] = s;
    }
    if (t < Hh) g_mean[t] = 0.0f;
}

// ---- table: fs(d) * cutoff(d), 8192 samples over [0, CUT] per layer ----
__global__ void table_kernel(const float* __restrict__ fW1,
                             const float* __restrict__ fb1) {
    int t = blockIdx.x * blockDim.x + threadIdx.x;
    if (t >= Ll * Kt) return;
    int l = t >> 13;
    int k = t & (Kt - 1);
    float d = k * (CUT / (float)(Kt - 1));
    float s = d * (2.0f / CUT) - 1.0f;
    const float* w1 = fW1 + l * Hh;
    const float* b1 = fb1 + l * Hh;
    const float* w2 = g_w2s + l * Hh;
    float acc = g_b2s[l];
    #pragma unroll 8
    for (int j = 0; j < Hh; j++)
        acc = fmaf(tanhf(fmaf(s, w1[j], b1[j])), w2[j], acc);
    float cut = 0.5f * (cosf(d * (float)(M_PI / 5.0)) + 1.0f);
    g_table[t] = acc * cut;
}

// ---- embedding: h = x @ emb_W + emb_b ----
__global__ void embed_kernel(const float* __restrict__ x,
                             const float* __restrict__ W,
                             const float* __restrict__ b) {
    __shared__ float sW[16 * 64];
    __shared__ float sb[64];
    int tid = threadIdx.x;
    for (int i = tid; i < 16 * 64; i += 256) sW[i] = W[i];
    if (tid < 64) sb[tid] = b[tid];
    __syncthreads();
    int t = blockIdx.x * 256 + tid;
    if (t >= Nn * 16) return;
    int n = t >> 4, q = t & 15, j0 = q * 4;
    const float* xr = x + n * 16;
    float4 acc = make_float4(sb[j0], sb[j0 + 1], sb[j0 + 2], sb[j0 + 3]);
    #pragma unroll
    for (int i = 0; i < 16; i++) {
        float xi = xr[i];
        acc.x = fmaf(xi, sW[i * 64 + j0 + 0], acc.x);
        acc.y = fmaf(xi, sW[i * 64 + j0 + 1], acc.y);
        acc.z = fmaf(xi, sW[i * 64 + j0 + 2], acc.z);
        acc.w = fmaf(xi, sW[i * 64 + j0 + 3], acc.w);
    }
    ((float4*)g_h)[t] = acc;
}

__global__ void zero_agg_kernel() {
    int t = blockIdx.x * blockDim.x + threadIdx.x;
    if (t < Nn * 16) ((float4*)g_agg)[t] = make_float4(0.f, 0.f, 0.f, 0.f);
}

// ---- edge pass: 16 threads/edge; gather h[col], scale by fs, red-add to agg[row]
__global__ void edge_kernel(const int* __restrict__ eidx,
                            const float* __restrict__ dist,
                            int l) {
    int t = blockIdx.x * blockDim.x + threadIdx.x;
    int e = t >> 4;
    if (e >= Ee) return;
    int sub = t & 15;
    int r = __ldg(eidx + e);
    int c = __ldg(eidx + Ee + e);
    float d = __ldg(dist + e);
    float u = d * ((float)(Kt - 1) / CUT);
    int i = (int)u;
    i = min(max(i, 0), Kt - 2);
    float fr = u - (float)i;
    const float* tb = g_table + l * Kt;
    float t0 = __ldg(tb + i), t1 = __ldg(tb + i + 1);
    float fs = fmaf(fr, t1 - t0, t0);
    float4 v = __ldg((const float4*)g_h + c * 16 + sub);
    v.x *= fs; v.y *= fs; v.z *= fs; v.w *= fs;
    red_add_v4((float4*)g_agg + r * 16 + sub, v);
}

// ---- node pass: out = softplus(agg@iW1+ib1)@iW2+ib2; h += BN(out). warp/node
__global__ void __launch_bounds__(128) node_kernel(
    const float* __restrict__ iW1, const float* __restrict__ ib1,
    const float* __restrict__ iW2, const float* __restrict__ ib2,
    const float* __restrict__ gam, const float* __restrict__ bet) {
    __shared__ float sW1[64 * 64], sW2[64 * 64];
    __shared__ float sb1[64], sb2[64], sg[64], sbt[64];
    __shared__ float sbuf[4][64];
    int tid = threadIdx.x;
    for (int i = tid; i < 4096; i += 128) { sW1[i] = iW1[i]; sW2[i] = iW2[i]; }
    if (tid < 64) { sb1[tid] = ib1[tid]; sb2[tid] = ib2[tid];
                    sg[tid] = gam[tid]; sbt[tid] = bet[tid]; }
    __syncthreads();
    int w = tid >> 5, lane = tid & 31;
    for (int n = blockIdx.x * 4 + w; n < Nn; n += gridDim.x * 4) {
        float a0 = g_agg[n * 64 + lane];
        float a1 = g_agg[n * 64 + 32 + lane];
        sbuf[w][lane] = a0; sbuf[w][lane + 32] = a1;
        __syncwarp();
        float acc0 = sb1[lane], acc1 = sb1[lane + 32];
        #pragma unroll
        for (int i = 0; i < 64; i++) {
            float ai = sbuf[w][i];
            acc0 = fmaf(ai, sW1[i * 64 + lane], acc0);
            acc1 = fmaf(ai, sW1[i * 64 + lane + 32], acc1);
        }
        acc0 = sp(acc0); acc1 = sp(acc1);
        __syncwarp();
        sbuf[w][lane] = acc0; sbuf[w][lane + 32] = acc1;
        __syncwarp();
        float o0 = sb2[lane], o1 = sb2[lane + 32];
        #pragma unroll
        for (int i = 0; i < 64; i++) {
            float ti = sbuf[w][i];
            o0 = fmaf(ti, sW2[i * 64 + lane], o0);
            o1 = fmaf(ti, sW2[i * 64 + lane + 32], o1);
        }
        o0 = fmaf(o0 * INVBN, sg[lane], sbt[lane]);
        o1 = fmaf(o1 * INVBN, sg[lane + 32], sbt[lane + 32]);
        g_h[n * 64 + lane] += o0;
        g_h[n * 64 + 32 + lane] += o1;
        __syncwarp();
    }
}

// ---- mean over nodes ----
__global__ void mean_kernel() {
    int tid = threadIdx.x;
    int j = tid & 63, rg = tid >> 6;
    float acc = 0.0f;
    for (int n = blockIdx.x * 4 + rg; n < Nn; n += gridDim.x * 4)
        acc += g_h[n * 64 + j];
    atomicAdd(&g_mean[j], acc);
}

// ---- final head: two dense(32)+softplus+BN, then dense(3) ----
__global__ void final_kernel(const float* __restrict__ oW1, const float* __restrict__ ob1,
                             const float* __restrict__ og1, const float* __restrict__ obt1,
                             const float* __restrict__ oW2, const float* __restrict__ ob2,
                             const float* __restrict__ og2, const float* __restrict__ obt2,
                             const float* __restrict__ fiW, const float* __restrict__ fib,
                             float* __restrict__ out) {
    __shared__ float gv[64], s1[32], s2[32];
    int t = threadIdx.x;  // 64 threads
    gv[t] = g_mean[t] * (1.0f / (float)Nn);
    __syncthreads();
    if (t < 32) {
        float acc = ob1[t];
        #pragma unroll
        for (int i = 0; i < 64; i++) acc = fmaf(gv[i], oW1[i * 32 + t], acc);
        s1[t] = fmaf(sp(acc) * INVBN, og1[t], obt1[t]);
    }
    __syncthreads();
    if (t < 32) {
        float acc = ob2[t];
        #pragma unroll
        for (int i = 0; i < 32; i++) acc = fmaf(s1[i], oW2[i * 32 + t], acc);
        s2[t] = fmaf(sp(acc) * INVBN, og2[t], obt2[t]);
    }
    __syncthreads();
    if (t < 3) {
        float acc = fib[t];
        #pragma unroll
        for (int i = 0; i < 32; i++) acc = fmaf(s2[i], fiW[i * 3 + t], acc);
        out[t] = acc;
    }
}

extern "C" void kernel_launch(void* const* d_in, const int* in_sizes, int n_in,
                              void* d_out, int out_size) {
    const float* x    = (const float*)d_in[0];
    const int*   eidx = (const int*)  d_in[1];
    const float* dist = (const float*)d_in[2];
    // d_in[3] edge_attr: unused by the math
    const float* embW = (const float*)d_in[4];
    const float* embB = (const float*)d_in[5];
    const float* fW1  = (const float*)d_in[6];
    const float* fb1  = (const float*)d_in[7];
    const float* fW2  = (const float*)d_in[8];
    const float* fb2  = (const float*)d_in[9];
    const float* iW1  = (const float*)d_in[10];
    const float* ib1  = (const float*)d_in[11];
    const float* iW2  = (const float*)d_in[12];
    const float* ib2  = (const float*)d_in[13];
    const float* gam  = (const float*)d_in[14];
    const float* bet  = (const float*)d_in[15];
    const float* oW1  = (const float*)d_in[16];
    const float* ob1  = (const float*)d_in[17];
    const float* og1  = (const float*)d_in[18];
    const float* obt1 = (const float*)d_in[19];
    const float* oW2  = (const float*)d_in[20];
    const float* ob2  = (const float*)d_in[21];
    const float* og2  = (const float*)d_in[22];
    const float* obt2 = (const float*)d_in[23];
    const float* fiW  = (const float*)d_in[24];
    const float* fib  = (const float*)d_in[25];
    float* out = (float*)d_out;

    prep_kernel<<<1, 256>>>(fW2, fb2);
    table_kernel<<<(Ll * Kt + 255) / 256, 256>>>(fW1, fb1);
    embed_kernel<<<(Nn * 16 + 255) / 256, 256>>>(x, embW, embB);

    for (int l = 0; l < Ll; l++) {
        zero_agg_kernel<<<(Nn * 16 + 255) / 256, 256>>>();
        edge_kernel<<<(Ee * 16 + 255) / 256, 256>>>(eidx, dist, l);
        node_kernel<<<1184, 128>>>(iW1 + l * 4096, ib1 + l * 64,
                                   iW2 + l * 4096, ib2 + l * 64,
                                   gam + l * 64, bet + l * 64);
    }

    mean_kernel<<<512, 256>>>();
    final_kernel<<<1, 64>>>(oW1, ob1, og1, obt1, oW2, ob2, og2, obt2,
                            fiW, fib, out);
}

// round 2
// speedup vs baseline: 1.4442x; 1.4442x over previous
#include <cuda_runtime.h>
#include <math.h>

#define Nn 100000
#define Ee 1600000
#define Hh 64
#define Ll 3
#define Kt 8192
#define CUT 5.0f
#define INVBN 0.9995003747f   // 1/sqrt(1+1e-3)
#define NB1 196               // ceil(Nn/512) scan blocks

// ---- static device scratch ----
__device__ __align__(256) float g_h[Nn * Hh];     // node features, 25.6 MB
__device__ __align__(256) float g_agg[Nn * Hh];   // aggregation target, 25.6 MB
__device__ __align__(256) int2  g_ep[Ee];         // CSR-permuted (col, u) 12.8 MB
__device__ int   g_cnt[Nn];                       // per-row degree
__device__ int   g_off[Nn];                       // CSR row offsets
__device__ int   g_cur[Nn];                       // fill cursors
__device__ int   g_bsum[NB1];                     // scan block totals
__device__ int   g_bpre[NB1];                     // scan block prefixes
__device__ float g_table[Ll * Kt];                // fs(d)*cut(d) per layer
__device__ float g_w2s[Ll * Hh];                  // rowsum of fW2
__device__ float g_b2s[Ll];                       // sum of fb2
__device__ float g_mean[Hh];                      // mean accumulator

__device__ __forceinline__ float sp(float x) {    // softplus, stable
    return fmaxf(x, 0.0f) + log1pf(expf(-fabsf(x)));
}

// ---- prep: fW2 rowsums, fb2 sums, zero mean accumulator ----
__global__ void prep_kernel(const float* __restrict__ fW2,
                            const float* __restrict__ fb2) {
    int t = threadIdx.x;
    if (t < Ll * Hh) {
        int l = t >> 6, j = t & 63;
        const float* p = fW2 + l * Hh * Hh + j * Hh;
        float s = 0.0f;
        #pragma unroll
        for (int k = 0; k < Hh; k++) s += p[k];
        g_w2s[t] = s;
    }
    if (t < Ll) {
        float s = 0.0f;
        for (int k = 0; k < Hh; k++) s += fb2[t * Hh + k];
        g_b2s[t] = s;
    }
    if (t < Hh) g_mean[t] = 0.0f;
}

// ---- table: fs(d) * cutoff(d), 8192 samples over [0, CUT] per layer ----
__global__ void table_kernel(const float* __restrict__ fW1,
                             const float* __restrict__ fb1) {
    int t = blockIdx.x * blockDim.x + threadIdx.x;
    if (t >= Ll * Kt) return;
    int l = t >> 13;
    int k = t & (Kt - 1);
    float d = k * (CUT / (float)(Kt - 1));
    float s = d * (2.0f / CUT) - 1.0f;
    const float* w1 = fW1 + l * Hh;
    const float* b1 = fb1 + l * Hh;
    const float* w2 = g_w2s + l * Hh;
    float acc = g_b2s[l];
    #pragma unroll 8
    for (int j = 0; j < Hh; j++)
        acc = fmaf(tanhf(fmaf(s, w1[j], b1[j])), w2[j], acc);
    float cut = 0.5f * (cosf(d * (float)(M_PI / 5.0)) + 1.0f);
    g_table[t] = acc * cut;
}

// ---- embedding: h = x @ emb_W + emb_b ----
__global__ void embed_kernel(const float* __restrict__ x,
                             const float* __restrict__ W,
                             const float* __restrict__ b) {
    __shared__ float sW[16 * 64];
    __shared__ float sb[64];
    int tid = threadIdx.x;
    for (int i = tid; i < 16 * 64; i += 256) sW[i] = W[i];
    if (tid < 64) sb[tid] = b[tid];
    __syncthreads();
    int t = blockIdx.x * 256 + tid;
    if (t >= Nn * 16) return;
    int n = t >> 4, q = t & 15, j0 = q * 4;
    const float* xr = x + n * 16;
    float4 acc = make_float4(sb[j0], sb[j0 + 1], sb[j0 + 2], sb[j0 + 3]);
    #pragma unroll
    for (int i = 0; i < 16; i++) {
        float xi = xr[i];
        acc.x = fmaf(xi, sW[i * 64 + j0 + 0], acc.x);
        acc.y = fmaf(xi, sW[i * 64 + j0 + 1], acc.y);
        acc.z = fmaf(xi, sW[i * 64 + j0 + 2], acc.z);
        acc.w = fmaf(xi, sW[i * 64 + j0 + 3], acc.w);
    }
    ((float4*)g_h)[t] = acc;
}

// ============ CSR build ============
__global__ void zcnt_kernel() {
    int i = blockIdx.x * blockDim.x + threadIdx.x;
    if (i < Nn) g_cnt[i] = 0;
}

__global__ void hist_kernel(const int* __restrict__ eidx) {
    int e = blockIdx.x * blockDim.x + threadIdx.x;
    if (e < Ee) atomicAdd(&g_cnt[eidx[e]], 1);
}

// block-level exclusive scan of g_cnt -> g_off (partial), totals -> g_bsum
__global__ void scan1_kernel() {
    int i = blockIdx.x * 512 + threadIdx.x;
    int v = (i < Nn) ? g_cnt[i] : 0;
    int lane = threadIdx.x & 31, w = threadIdx.x >> 5;
    int x = v;
    #pragma unroll
    for (int off = 1; off < 32; off <<= 1) {
        int y = __shfl_up_sync(0xffffffff, x, off);
        if (lane >= off) x += y;
    }
    __shared__ int wsum[16], wpre[16];
    if (lane == 31) wsum[w] = x;
    __syncthreads();
    if (threadIdx.x < 16) {
        int s = wsum[threadIdx.x];
        int xs = s;
        #pragma unroll
        for (int off = 1; off < 16; off <<= 1) {
            int y = __shfl_up_sync(0x0000ffff, xs, off);
            if ((int)threadIdx.x >= off) xs += y;
        }
        wpre[threadIdx.x] = xs - s;
        if (threadIdx.x == 15) g_bsum[blockIdx.x] = xs;
    }
    __syncthreads();
    if (i < Nn) g_off[i] = x - v + wpre[w];
}

// scan block totals (single block, 256 threads, NB1 <= 256)
__global__ void scan2_kernel() {
    int t = threadIdx.x;
    int v = (t < NB1) ? g_bsum[t] : 0;
    int lane = t & 31, w = t >> 5;
    int x = v;
    #pragma unroll
    for (int off = 1; off < 32; off <<= 1) {
        int y = __shfl_up_sync(0xffffffff, x, off);
        if (lane >= off) x += y;
    }
    __shared__ int wsum[8], wpre[8];
    if (lane == 31) wsum[w] = x;
    __syncthreads();
    if (t < 8) {
        int s = wsum[t];
        int xs = s;
        #pragma unroll
        for (int off = 1; off < 8; off <<= 1) {
            int y = __shfl_up_sync(0x000000ff, xs, off);
            if (t >= off) xs += y;
        }
        wpre[t] = xs - s;
    }
    __syncthreads();
    if (t < NB1) g_bpre[t] = x - v + wpre[w];
}

__global__ void scan3_kernel() {
    int i = blockIdx.x * 512 + threadIdx.x;
    if (i < Nn) {
        int o = g_off[i] + g_bpre[blockIdx.x];
        g_off[i] = o;
        g_cur[i] = o;
    }
}

// scatter edges into CSR order; store (col, table coordinate u)
__global__ void fill_kernel(const int* __restrict__ eidx,
                            const float* __restrict__ dist) {
    int e = blockIdx.x * blockDim.x + threadIdx.x;
    if (e >= Ee) return;
    int r = eidx[e];
    int c = eidx[Ee + e];
    float d = __ldg(dist + e);
    float u = d * ((float)(Kt - 1) / CUT);
    u = fminf(fmaxf(u, 0.0f), (float)(Kt - 2) + 0.999f);
    int pos = atomicAdd(&g_cur[r], 1);
    g_ep[pos] = make_int2(c, __float_as_int(u));
}

// ============ per-layer edge aggregation: warp per row, no atomics ============
__global__ void __launch_bounds__(256) agg_kernel(int l) {
    int gw = (blockIdx.x * 256 + threadIdx.x) >> 5;
    if (gw >= Nn) return;
    int lane = threadIdx.x & 31, sub = lane & 15, par = lane >> 4;
    const float* tb = g_table + l * Kt;
    int beg = g_off[gw], end = beg + g_cnt[gw];
    float4 acc = make_float4(0.f, 0.f, 0.f, 0.f);
    for (int e = beg + par; e < end; e += 2) {
        int2 m = __ldg(&g_ep[e]);
        float u = __int_as_float(m.y);
        int i = (int)u;
        float fr = u - (float)i;
        float t0 = __ldg(tb + i), t1 = __ldg(tb + i + 1);
        float fs = fmaf(fr, t1 - t0, t0);
        float4 v = __ldg((const float4*)g_h + m.x * 16 + sub);
        acc.x = fmaf(v.x, fs, acc.x);
        acc.y = fmaf(v.y, fs, acc.y);
        acc.z = fmaf(v.z, fs, acc.z);
        acc.w = fmaf(v.w, fs, acc.w);
    }
    acc.x += __shfl_xor_sync(0xffffffff, acc.x, 16);
    acc.y += __shfl_xor_sync(0xffffffff, acc.y, 16);
    acc.z += __shfl_xor_sync(0xffffffff, acc.z, 16);
    acc.w += __shfl_xor_sync(0xffffffff, acc.w, 16);
    if (par == 0) ((float4*)g_agg)[gw * 16 + sub] = acc;
}

// ============ node MLP: register-resident weights, thread-per-column ============
__global__ void __launch_bounds__(128, 3) node_kernel(
    const float* __restrict__ iW1, const float* __restrict__ ib1,
    const float* __restrict__ iW2, const float* __restrict__ ib2,
    const float* __restrict__ gam, const float* __restrict__ bet) {
    __shared__ float sa[2][64];
    __shared__ float st[2][64];
    int tid = threadIdx.x;
    int half = tid >> 6, j = tid & 63;
    float w1[64], w2[64];
    #pragma unroll
    for (int i = 0; i < 64; i++) {
        w1[i] = iW1[i * 64 + j];
        w2[i] = iW2[i * 64 + j];
    }
    float b1 = ib1[j], b2 = ib2[j];
    float gm = gam[j] * INVBN, bt = bet[j];

    for (int n0 = blockIdx.x * 2; n0 < Nn; n0 += gridDim.x * 2) {
        int n = n0 + half;              // Nn even -> always valid
        sa[half][j] = g_agg[n * 64 + j];
        __syncthreads();
        float acc = b1;
        const float4* A4 = (const float4*)sa[half];
        #pragma unroll
        for (int i4 = 0; i4 < 16; i4++) {
            float4 av = A4[i4];
            acc = fmaf(av.x, w1[i4 * 4 + 0], acc);
            acc = fmaf(av.y, w1[i4 * 4 + 1], acc);
            acc = fmaf(av.z, w1[i4 * 4 + 2], acc);
            acc = fmaf(av.w, w1[i4 * 4 + 3], acc);
        }
        acc = sp(acc);
        st[half][j] = acc;
        __syncthreads();
        float o = b2;
        const float4* T4 = (const float4*)st[half];
        #pragma unroll
        for (int i4 = 0; i4 < 16; i4++) {
            float4 tv = T4[i4];
            o = fmaf(tv.x, w2[i4 * 4 + 0], o);
            o = fmaf(tv.y, w2[i4 * 4 + 1], o);
            o = fmaf(tv.z, w2[i4 * 4 + 2], o);
            o = fmaf(tv.w, w2[i4 * 4 + 3], o);
        }
        g_h[n * 64 + j] += fmaf(o, gm, bt);
    }
}

// ---- mean over nodes ----
__global__ void mean_kernel() {
    int tid = threadIdx.x;
    int j = tid & 63, rg = tid >> 6;
    float acc = 0.0f;
    for (int n = blockIdx.x * 4 + rg; n < Nn; n += gridDim.x * 4)
        acc += g_h[n * 64 + j];
    atomicAdd(&g_mean[j], acc);
}

// ---- final head: two dense(32)+softplus+BN, then dense(3) ----
__global__ void final_kernel(const float* __restrict__ oW1, const float* __restrict__ ob1,
                             const float* __restrict__ og1, const float* __restrict__ obt1,
                             const float* __restrict__ oW2, const float* __restrict__ ob2,
                             const float* __restrict__ og2, const float* __restrict__ obt2,
                             const float* __restrict__ fiW, const float* __restrict__ fib,
                             float* __restrict__ out) {
    __shared__ float gv[64], s1[32], s2[32];
    int t = threadIdx.x;  // 64 threads
    gv[t] = g_mean[t] * (1.0f / (float)Nn);
    __syncthreads();
    if (t < 32) {
        float acc = ob1[t];
        #pragma unroll
        for (int i = 0; i < 64; i++) acc = fmaf(gv[i], oW1[i * 32 + t], acc);
        s1[t] = fmaf(sp(acc) * INVBN, og1[t], obt1[t]);
    }
    __syncthreads();
    if (t < 32) {
        float acc = ob2[t];
        #pragma unroll
        for (int i = 0; i < 32; i++) acc = fmaf(s1[i], oW2[i * 32 + t], acc);
        s2[t] = fmaf(sp(acc) * INVBN, og2[t], obt2[t]);
    }
    __syncthreads();
    if (t < 3) {
        float acc = fib[t];
        #pragma unroll
        for (int i = 0; i < 32; i++) acc = fmaf(s2[i], fiW[i * 3 + t], acc);
        out[t] = acc;
    }
}

extern "C" void kernel_launch(void* const* d_in, const int* in_sizes, int n_in,
                              void* d_out, int out_size) {
    const float* x    = (const float*)d_in[0];
    const int*   eidx = (const int*)  d_in[1];
    const float* dist = (const float*)d_in[2];
    // d_in[3] edge_attr: unused by the math
    const float* embW = (const float*)d_in[4];
    const float* embB = (const float*)d_in[5];
    const float* fW1  = (const float*)d_in[6];
    const float* fb1  = (const float*)d_in[7];
    const float* fW2  = (const float*)d_in[8];
    const float* fb2  = (const float*)d_in[9];
    const float* iW1  = (const float*)d_in[10];
    const float* ib1  = (const float*)d_in[11];
    const float* iW2  = (const float*)d_in[12];
    const float* ib2  = (const float*)d_in[13];
    const float* gam  = (const float*)d_in[14];
    const float* bet  = (const float*)d_in[15];
    const float* oW1  = (const float*)d_in[16];
    const float* ob1  = (const float*)d_in[17];
    const float* og1  = (const float*)d_in[18];
    const float* obt1 = (const float*)d_in[19];
    const float* oW2  = (const float*)d_in[20];
    const float* ob2  = (const float*)d_in[21];
    const float* og2  = (const float*)d_in[22];
    const float* obt2 = (const float*)d_in[23];
    const float* fiW  = (const float*)d_in[24];
    const float* fib  = (const float*)d_in[25];
    float* out = (float*)d_out;

    prep_kernel<<<1, 256>>>(fW2, fb2);
    table_kernel<<<(Ll * Kt + 255) / 256, 256>>>(fW1, fb1);
    embed_kernel<<<(Nn * 16 + 255) / 256, 256>>>(x, embW, embB);

    // CSR build (once per call, reused across the 3 layers)
    zcnt_kernel<<<(Nn + 1023) / 1024, 1024>>>();
    hist_kernel<<<(Ee + 255) / 256, 256>>>(eidx);
    scan1_kernel<<<NB1, 512>>>();
    scan2_kernel<<<1, 256>>>();
    scan3_kernel<<<NB1, 512>>>();
    fill_kernel<<<(Ee + 255) / 256, 256>>>(eidx, dist);

    for (int l = 0; l < Ll; l++) {
        agg_kernel<<<(Nn * 32 + 255) / 256, 256>>>(l);
        node_kernel<<<444, 128>>>(iW1 + l * 4096, ib1 + l * 64,
                                  iW2 + l * 4096, ib2 + l * 64,
                                  gam + l * 64, bet + l * 64);
    }

    mean_kernel<<<512, 256>>>();
    final_kernel<<<1, 64>>>(oW1, ob1, og1, obt1, oW2, ob2, og2, obt2,
                            fiW, fib, out);
}